// round 11
// baseline (speedup 1.0000x reference)
#include <cuda_runtime.h>
#include <cuda_bf16.h>
#include <cstdint>

#define NPTS  32768
#define P     16
#define NC    8192
#define E     (NC * P)
#define IN_F  64
#define OUT_F 128
#define TMR   64                  // centers per CTA
#define KC    8                   // kernel points per CTA (k-split 2)
#define LDA   144u

// smem layout (bytes):
// A stage s: Ah @ s*18432, Al @ +9216          (64 rows x 144B each)
// W stage s: Wh @ 36864 + s*36864, Wl @ +18432 (128 rows x 144B each)
#define A_OFF(s)  ((uint32_t)(s) * 18432u)
#define AL_D      9216u
#define W_OFF(s)  (36864u + (uint32_t)(s) * 36864u)
#define WL_D      18432u
#define SMEM_DYN  110592

// Scratch
__device__ float    g_coef[E];
__device__ float    g_part[NC * OUT_F];    // k-half 1 partial
__device__ uint32_t g_wimg[P * 2 * 4096];  // per k: hi[128n][32w] then lo (Wt[n][i] bf16)

// ---------------------------------------------------------------------------
// helpers
// ---------------------------------------------------------------------------
__device__ __forceinline__ uint32_t smem_u32(const void* p) {
    uint32_t a;
    asm("{ .reg .u64 t; cvta.to.shared.u64 t, %1; cvt.u32.u64 %0, t; }"
        : "=r"(a) : "l"(p));
    return a;
}
__device__ __forceinline__ uint32_t pack_hi(float a, float b, float& ra, float& rb) {
    __nv_bfloat16 ha = __float2bfloat16(a);
    __nv_bfloat16 hb = __float2bfloat16(b);
    ra = a - __bfloat162float(ha);
    rb = b - __bfloat162float(hb);
    return (uint32_t)__bfloat16_as_ushort(ha) | ((uint32_t)__bfloat16_as_ushort(hb) << 16);
}
__device__ __forceinline__ uint32_t pack2(float a, float b) {
    uint32_t r;
    asm("cvt.rn.bf16x2.f32 %0, %1, %2;" : "=r"(r) : "f"(b), "f"(a));
    return r;
}
__device__ __forceinline__ void cp_async16(uint32_t dst, const void* g) {
    asm volatile("cp.async.cg.shared.global [%0], [%1], 16;" :: "r"(dst), "l"(g));
}

#define LDSM4(r, addr) asm volatile( \
    "ldmatrix.sync.aligned.m8n8.x4.shared.b16 {%0,%1,%2,%3}, [%4];" \
    : "=r"((r)[0]), "=r"((r)[1]), "=r"((r)[2]), "=r"((r)[3]) : "r"(addr))
#define MMA(d, a, b0, b1) asm volatile( \
    "mma.sync.aligned.m16n8k16.row.col.f32.bf16.bf16.f32 " \
    "{%0,%1,%2,%3},{%4,%5,%6,%7},{%8,%9},{%0,%1,%2,%3};" \
    : "+f"((d)[0]), "+f"((d)[1]), "+f"((d)[2]), "+f"((d)[3]) \
    : "r"((a)[0]), "r"((a)[1]), "r"((a)[2]), "r"((a)[3]), "r"(b0), "r"(b1))

// ---------------------------------------------------------------------------
// Pass 1 (fused): blocks [0,512) geometry coefficients; blocks [512,768) build
// bf16 hi/lo transposed W images Wt[n][i].
// ---------------------------------------------------------------------------
__global__ void __launch_bounds__(256) kp_prep_kernel(
    const float* __restrict__ pos,
    const int*   __restrict__ edge_src,
    const int*   __restrict__ edge_tgt,
    const float* __restrict__ kpts,
    const float* __restrict__ kw)
{
    if (blockIdx.x < 512) {
        int e    = blockIdx.x * 256 + threadIdx.x;
        int lane = threadIdx.x & 31;

        // pos_i is identical across each 16-lane group: load once, broadcast.
        float px, py, pz;
        if ((lane & 15) == 0) {
            int ti = edge_tgt[e];
            px = pos[ti * 3 + 0]; py = pos[ti * 3 + 1]; pz = pos[ti * 3 + 2];
        }
        int base = lane & 16;
        px = __shfl_sync(0xffffffffu, px, base);
        py = __shfl_sync(0xffffffffu, py, base);
        pz = __shfl_sync(0xffffffffu, pz, base);

        int si = edge_src[e];
        float rx = px - pos[si * 3 + 0];
        float ry = py - pos[si * 3 + 1];
        float rz = pz - pos[si * 3 + 2];

        float best = 3.402823466e38f;
        int   nn   = 0;
#pragma unroll
        for (int k = 0; k < P; ++k) {
            float dx = rx - kpts[k * 3 + 0];
            float dy = ry - kpts[k * 3 + 1];
            float dz = rz - kpts[k * 3 + 2];
            float d2 = dx * dx + dy * dy + dz * dz;
            if (d2 < best) { best = d2; nn = k; }   // strict < == jnp.argmin
        }
        float w = fmaxf(1.0f - sqrtf(best) * 1.5f, 0.0f);   // 1/KP_EXTENT = 1.5

        int   myk  = lane & 15;
        float coef = 0.0f;
#pragma unroll
        for (int j = 0; j < 16; ++j) {
            int   nnj = __shfl_sync(0xffffffffu, nn, base + j);
            float wj  = __shfl_sync(0xffffffffu, w,  base + j);
            if (nnj == myk) coef += wj;
        }
        g_coef[e] = coef;
    } else {
        // Wt[n][i] bf16 hi/lo: word (k, n, i2) holds elems i=2*i2, 2*i2+1.
        int t  = (blockIdx.x - 512) * 256 + threadIdx.x;    // [0, 65536)
        int n  = t & 127;
        int i2 = (t >> 7) & 31;
        int k  = t >> 12;
        const float* wp = kw + ((size_t)k * IN_F + 2 * i2) * OUT_F + n;
        float w0 = wp[0], w1 = wp[OUT_F];
        float r0, r1;
        uint32_t hi = pack_hi(w0, w1, r0, r1);
        uint32_t lo = pack2(r0, r1);
        g_wimg[(k * 2 + 0) * 4096 + n * 32 + i2] = hi;
        g_wimg[(k * 2 + 1) * 4096 + n * 32 + i2] = lo;
    }
}

// ---------------------------------------------------------------------------
// Pass 2: mma.sync bf16 3-pass, k-split 2. 256 CTAs x 256 thr (2 CTAs/SM).
// CTA (tile, kc): 64 centers x 128 cols, k in [kc*8, kc*8+8).
// Warp grid 2x4: warp (wm, wn) covers rows [wm*32,+32), cols [wn*32,+32).
// ONE __syncthreads per k: next A/W staged into the opposite buffer while
// this k's MMAs run. kc=0 writes out, kc=1 writes g_part.
// ---------------------------------------------------------------------------
__global__ void __launch_bounds__(256, 2) kp_mma_kernel(
    const float* __restrict__ x,
    const int*   __restrict__ edge_src,
    float*       __restrict__ out)
{
    extern __shared__ __align__(128) char smem[];
    const uint32_t sb   = smem_u32(smem);
    const int      tid  = threadIdx.x;
    const int      lane = tid & 31;
    const int      w    = tid >> 5;
    const int      wm   = w >> 2;            // 0..1
    const int      wn   = w & 3;             // 0..3
    const int      tile = blockIdx.x >> 1;
    const int      kc   = blockIdx.x & 1;
    const int      c0   = tile * TMR;
    const int      k0   = kc * KC;

    // A-build mapping: 4 threads per row; thread covers 16 floats (32B bf16)
    const int ar = tid >> 2;          // row 0..63
    const int ap = tid & 3;           // part: floats [ap*16, ap*16+16)

    float acc[2][4][4];
#pragma unroll
    for (int mt = 0; mt < 2; ++mt)
#pragma unroll
        for (int nt = 0; nt < 4; ++nt)
#pragma unroll
            for (int q = 0; q < 4; ++q) acc[mt][nt][q] = 0.0f;

    const int*   srow = edge_src + (size_t)(c0 + ar) * P + k0;
    const float* crow = g_coef + (size_t)(c0 + ar) * P + k0;

    // STS A hi/lo into stage st from registers.
    auto sts_a = [&](uint32_t st, const float4* xv, float c) {
        float a0 = xv[0].x * c, a1 = xv[0].y * c, a2 = xv[0].z * c, a3 = xv[0].w * c;
        float a4 = xv[1].x * c, a5 = xv[1].y * c, a6 = xv[1].z * c, a7 = xv[1].w * c;
        float b0 = xv[2].x * c, b1 = xv[2].y * c, b2 = xv[2].z * c, b3 = xv[2].w * c;
        float b4 = xv[3].x * c, b5 = xv[3].y * c, b6 = xv[3].z * c, b7 = xv[3].w * c;
        float r0, r1, r2, r3, r4, r5, r6, r7;
        float t0, t1, t2, t3, t4, t5, t6, t7;
        uint4 h0, h1, l0, l1;
        h0.x = pack_hi(a0, a1, r0, r1); h0.y = pack_hi(a2, a3, r2, r3);
        h0.z = pack_hi(a4, a5, r4, r5); h0.w = pack_hi(a6, a7, r6, r7);
        h1.x = pack_hi(b0, b1, t0, t1); h1.y = pack_hi(b2, b3, t2, t3);
        h1.z = pack_hi(b4, b5, t4, t5); h1.w = pack_hi(b6, b7, t6, t7);
        l0.x = pack2(r0, r1); l0.y = pack2(r2, r3);
        l0.z = pack2(r4, r5); l0.w = pack2(r6, r7);
        l1.x = pack2(t0, t1); l1.y = pack2(t2, t3);
        l1.z = pack2(t4, t5); l1.w = pack2(t6, t7);
        char* pa = smem + A_OFF(st) + (uint32_t)ar * LDA + (uint32_t)ap * 32;
        *(uint4*)(pa)             = h0;
        *(uint4*)(pa + 16)        = h1;
        *(uint4*)(pa + AL_D)      = l0;
        *(uint4*)(pa + AL_D + 16) = l1;
    };
    // cp.async W[k0+kk] (hi+lo, each 1024 16B-chunks) + commit.
    auto cp_w = [&](uint32_t st, int kk) {
        int kidx = k0 + kk;
#pragma unroll
        for (int hl = 0; hl < 2; ++hl) {
            uint32_t    wd = sb + W_OFF(st) + hl * WL_D;
            const char* ws = (const char*)(g_wimg + ((size_t)kidx * 2 + hl) * 4096);
#pragma unroll
            for (int jj = 0; jj < 4; ++jj) {
                int j = tid + 256 * jj;   // [0, 1024)
                cp_async16(wd + (uint32_t)(j >> 3) * LDA + (uint32_t)(j & 7) * 16,
                           ws + (size_t)j * 16);
            }
        }
        asm volatile("cp.async.commit_group;" ::: "memory");
    };

    // Prologue: A[0]/W[0] -> stage0, prefetch xv for kk=1, wait + barrier.
    float4 xv[4];
    {
        int src0 = srow[0];
        const float4* xr = (const float4*)(x + (size_t)src0 * IN_F) + ap * 4;
#pragma unroll
        for (int q = 0; q < 4; ++q) xv[q] = xr[q];
        sts_a(0, xv, crow[0]);
    }
    cp_w(0, 0);
    {
        int src1 = srow[1];
        const float4* xr = (const float4*)(x + (size_t)src1 * IN_F) + ap * 4;
#pragma unroll
        for (int q = 0; q < 4; ++q) xv[q] = xr[q];
    }
    asm volatile("cp.async.wait_group 0;" ::: "memory");
    __syncthreads();

#pragma unroll 1
    for (int k = 0; k < KC; ++k) {
        const uint32_t s  = (uint32_t)(k & 1);
        const uint32_t ns = s ^ 1u;
        const int      kn = (k + 1) & (KC - 1);   // next k within this half

        // W[next]/A[next] -> stage ns (overlaps with this k's MMAs).
        cp_w(ns, kn);
        sts_a(ns, xv, crow[kn]);
        // Prefetch xv for k+2.
        {
            int srcn = srow[(k + 2) & (KC - 1)];
            const float4* xr = (const float4*)(x + (size_t)srcn * IN_F) + ap * 4;
#pragma unroll
            for (int q = 0; q < 4; ++q) xv[q] = xr[q];
        }

        // MMA over stage s: 4 ksteps of 16, warp tile 32x32.
        const uint32_t aBase = sb + A_OFF(s) +
            (uint32_t)(wm * 32 + (lane & 15)) * LDA + (uint32_t)(lane >> 4) * 16;
        const uint32_t bBase = sb + W_OFF(s) +
            (uint32_t)(wn * 32 + ((lane >> 4) << 3) + (lane & 7)) * LDA +
            (uint32_t)((lane >> 3) & 1) * 16;
#pragma unroll
        for (int ks = 0; ks < 4; ++ks) {
            uint32_t ah[2][4], al[2][4], bh[2][4], bl[2][4];
            uint32_t ao = aBase + (uint32_t)ks * 32;
            uint32_t bo = bBase + (uint32_t)ks * 32;
            LDSM4(ah[0], ao);
            LDSM4(ah[1], ao + 16 * LDA);
            LDSM4(bh[0], bo);
            LDSM4(bh[1], bo + 16 * LDA);
            LDSM4(al[0], ao + AL_D);
            LDSM4(al[1], ao + AL_D + 16 * LDA);
            LDSM4(bl[0], bo + WL_D);
            LDSM4(bl[1], bo + WL_D + 16 * LDA);

            // Pass-outer order: 8 independent accumulators between reuses.
#pragma unroll
            for (int mt = 0; mt < 2; ++mt)
#pragma unroll
                for (int nt = 0; nt < 4; ++nt)
                    MMA(acc[mt][nt], ah[mt], bh[nt >> 1][2 * (nt & 1)],
                                             bh[nt >> 1][2 * (nt & 1) + 1]);
#pragma unroll
            for (int mt = 0; mt < 2; ++mt)
#pragma unroll
                for (int nt = 0; nt < 4; ++nt)
                    MMA(acc[mt][nt], ah[mt], bl[nt >> 1][2 * (nt & 1)],
                                             bl[nt >> 1][2 * (nt & 1) + 1]);
#pragma unroll
            for (int mt = 0; mt < 2; ++mt)
#pragma unroll
                for (int nt = 0; nt < 4; ++nt)
                    MMA(acc[mt][nt], al[mt], bh[nt >> 1][2 * (nt & 1)],
                                             bh[nt >> 1][2 * (nt & 1) + 1]);
        }

        // Wait for next W then release both stages.
        asm volatile("cp.async.wait_group 0;" ::: "memory");
        __syncthreads();
    }

    // Epilogue: write [64,128] tile. kc=0 -> out, kc=1 -> partial.
    float* dst = (kc == 0) ? out : g_part;
#pragma unroll
    for (int mt = 0; mt < 2; ++mt)
#pragma unroll
        for (int nt = 0; nt < 4; ++nt) {
            int    row = c0 + wm * 32 + mt * 16 + (lane >> 2);
            int    col = wn * 32 + nt * 8 + (lane & 3) * 2;
            float* o   = dst + (size_t)row * OUT_F + col;
            *(float2*)o               = make_float2(acc[mt][nt][0], acc[mt][nt][1]);
            *(float2*)(o + 8 * OUT_F) = make_float2(acc[mt][nt][2], acc[mt][nt][3]);
        }
}

// ---------------------------------------------------------------------------
// Pass 3: fold k-half partial into out (262144 float4).
// ---------------------------------------------------------------------------
__global__ void __launch_bounds__(256) kp_reduce_kernel(float* __restrict__ out)
{
    int idx = blockIdx.x * 256 + threadIdx.x;
    const float4* p = (const float4*)g_part;
    float4* o = (float4*)out;
    float4 v = o[idx];
    float4 a = p[idx];
    v.x += a.x; v.y += a.y; v.z += a.z; v.w += a.w;
    o[idx] = v;
}

extern "C" void kernel_launch(void* const* d_in, const int* in_sizes, int n_in,
                              void* d_out, int out_size)
{
    const float* x        = (const float*)d_in[0];
    const float* pos      = (const float*)d_in[1];
    const int*   edge_src = (const int*)  d_in[2];
    const int*   edge_tgt = (const int*)  d_in[3];
    const float* kpts     = (const float*)d_in[4];
    const float* kw       = (const float*)d_in[5];
    float*       out      = (float*)d_out;

    cudaFuncSetAttribute(kp_mma_kernel,
                         cudaFuncAttributeMaxDynamicSharedMemorySize, SMEM_DYN);

    kp_prep_kernel<<<768, 256>>>(pos, edge_src, edge_tgt, kpts, kw);
    kp_mma_kernel<<<(NC / TMR) * 2, 256, SMEM_DYN>>>(x, edge_src, out);
    kp_reduce_kernel<<<NC * OUT_F / 4 / 256, 256>>>(out);
}

// round 12
// speedup vs baseline: 1.0060x; 1.0060x over previous
#include <cuda_runtime.h>
#include <cuda_bf16.h>
#include <cstdint>

#define NPTS  32768
#define P     16
#define NC    8192
#define E     (NC * P)
#define IN_F  64
#define OUT_F 128
#define TMR   32                  // centers per CTA
#define LDA   144u

// smem layout (bytes):
// A stage s: Ah @ s*9216, Al @ +4608          (32 rows x 144B each)
// W stage s: Wh @ 18432 + s*36864, Wl @ +18432 (128 rows x 144B each)
#define A_OFF(s)  ((uint32_t)(s) * 9216u)
#define AL_D      4608u
#define W_OFF(s)  (18432u + (uint32_t)(s) * 36864u)
#define WL_D      18432u
#define SMEM_DYN  92160

// Scratch
__device__ float    g_coef[E];
__device__ uint32_t g_wimg[P * 2 * 4096];  // per k: hi[128n][32w] then lo (Wt[n][i] bf16)

// ---------------------------------------------------------------------------
// helpers
// ---------------------------------------------------------------------------
__device__ __forceinline__ uint32_t smem_u32(const void* p) {
    uint32_t a;
    asm("{ .reg .u64 t; cvta.to.shared.u64 t, %1; cvt.u32.u64 %0, t; }"
        : "=r"(a) : "l"(p));
    return a;
}
__device__ __forceinline__ uint32_t pack_hi(float a, float b, float& ra, float& rb) {
    __nv_bfloat16 ha = __float2bfloat16(a);
    __nv_bfloat16 hb = __float2bfloat16(b);
    ra = a - __bfloat162float(ha);
    rb = b - __bfloat162float(hb);
    return (uint32_t)__bfloat16_as_ushort(ha) | ((uint32_t)__bfloat16_as_ushort(hb) << 16);
}
__device__ __forceinline__ uint32_t pack2(float a, float b) {
    uint32_t r;
    asm("cvt.rn.bf16x2.f32 %0, %1, %2;" : "=r"(r) : "f"(b), "f"(a));
    return r;
}
__device__ __forceinline__ void cp_async16(uint32_t dst, const void* g) {
    asm volatile("cp.async.cg.shared.global [%0], [%1], 16;" :: "r"(dst), "l"(g));
}

#define LDSM4(r, addr) asm volatile( \
    "ldmatrix.sync.aligned.m8n8.x4.shared.b16 {%0,%1,%2,%3}, [%4];" \
    : "=r"((r)[0]), "=r"((r)[1]), "=r"((r)[2]), "=r"((r)[3]) : "r"(addr))
#define MMA(d, a, b0, b1) asm volatile( \
    "mma.sync.aligned.m16n8k16.row.col.f32.bf16.bf16.f32 " \
    "{%0,%1,%2,%3},{%4,%5,%6,%7},{%8,%9},{%0,%1,%2,%3};" \
    : "+f"((d)[0]), "+f"((d)[1]), "+f"((d)[2]), "+f"((d)[3]) \
    : "r"((a)[0]), "r"((a)[1]), "r"((a)[2]), "r"((a)[3]), "r"(b0), "r"(b1))

// ---------------------------------------------------------------------------
// Pass 1 (fused): blocks [0,512) geometry; blocks [512,576) build bf16 hi/lo
// transposed W images Wt[n][i] with COALESCED reads AND writes (smem staging).
// W block b (0..63): k = b>>2, i2-quarter q = b&3 covers i2 in [q*8, q*8+8).
// ---------------------------------------------------------------------------
__global__ void __launch_bounds__(256) kp_prep_kernel(
    const float* __restrict__ pos,
    const int*   __restrict__ edge_src,
    const int*   __restrict__ edge_tgt,
    const float* __restrict__ kpts,
    const float* __restrict__ kw)
{
    if (blockIdx.x < 512) {
        int e    = blockIdx.x * 256 + threadIdx.x;
        int lane = threadIdx.x & 31;

        // pos_i is identical across each 16-lane group: load once, broadcast.
        float px, py, pz;
        if ((lane & 15) == 0) {
            int ti = edge_tgt[e];
            px = pos[ti * 3 + 0]; py = pos[ti * 3 + 1]; pz = pos[ti * 3 + 2];
        }
        int base = lane & 16;
        px = __shfl_sync(0xffffffffu, px, base);
        py = __shfl_sync(0xffffffffu, py, base);
        pz = __shfl_sync(0xffffffffu, pz, base);

        int si = edge_src[e];
        float rx = px - pos[si * 3 + 0];
        float ry = py - pos[si * 3 + 1];
        float rz = pz - pos[si * 3 + 2];

        float best = 3.402823466e38f;
        int   nn   = 0;
#pragma unroll
        for (int k = 0; k < P; ++k) {
            float dx = rx - kpts[k * 3 + 0];
            float dy = ry - kpts[k * 3 + 1];
            float dz = rz - kpts[k * 3 + 2];
            float d2 = dx * dx + dy * dy + dz * dz;
            if (d2 < best) { best = d2; nn = k; }   // strict < == jnp.argmin
        }
        float w = fmaxf(1.0f - sqrtf(best) * 1.5f, 0.0f);   // 1/KP_EXTENT = 1.5

        int   myk  = lane & 15;
        float coef = 0.0f;
#pragma unroll
        for (int j = 0; j < 16; ++j) {
            int   nnj = __shfl_sync(0xffffffffu, nn, base + j);
            float wj  = __shfl_sync(0xffffffffu, w,  base + j);
            if (nnj == myk) coef += wj;
        }
        g_coef[e] = coef;
    } else {
        __shared__ uint32_t th[128][9];    // hi staging: [n][i2-local], padded
        __shared__ uint32_t tl[128][9];    // lo staging
        int b = blockIdx.x - 512;          // 0..63
        int k = b >> 2;
        int q = b & 3;
        int tid = threadIdx.x;

        // Phase 1: coalesced kw reads (n fast), stage into smem.
#pragma unroll
        for (int it = 0; it < 4; ++it) {
            int idx = it * 256 + tid;      // [0, 1024)
            int n   = idx & 127;
            int i2l = idx >> 7;            // 0..7
            int i2  = q * 8 + i2l;
            const float* wp = kw + ((size_t)k * IN_F + 2 * i2) * OUT_F + n;
            float w0 = wp[0], w1 = wp[OUT_F];
            float r0, r1;
            uint32_t hi = pack_hi(w0, w1, r0, r1);
            uint32_t lo = pack2(r0, r1);
            th[n][i2l] = hi;
            tl[n][i2l] = lo;
        }
        __syncthreads();

        // Phase 2: coalesced g_wimg writes (i2 fast within 32B segments).
        uint32_t* gh = g_wimg + (size_t)(k * 2 + 0) * 4096;
        uint32_t* gl = g_wimg + (size_t)(k * 2 + 1) * 4096;
#pragma unroll
        for (int it = 0; it < 4; ++it) {
            int idx = it * 256 + tid;      // [0, 1024)
            int n   = idx >> 3;
            int i2l = idx & 7;
            gh[n * 32 + q * 8 + i2l] = th[n][i2l];
            gl[n * 32 + q * 8 + i2l] = tl[n][i2l];
        }
    }
}

// ---------------------------------------------------------------------------
// Pass 2: mma.sync bf16 3-pass. 256 CTAs x 256 thr (2 CTAs/SM).
// CTA: 32 centers x 128 cols, ALL 16 kernel points in register accumulators
// (no k-split, no reduce). 8 warps: warp w covers rows [0,32), cols [w*16,+16).
// ONE __syncthreads per k: A[k+1]/W[k+1] staged into the opposite buffer
// while k's MMAs run.
// ---------------------------------------------------------------------------
__global__ void __launch_bounds__(256, 2) kp_mma_kernel(
    const float* __restrict__ x,
    const int*   __restrict__ edge_src,
    float*       __restrict__ out)
{
    extern __shared__ __align__(128) char smem[];
    const uint32_t sb   = smem_u32(smem);
    const int      tid  = threadIdx.x;
    const int      lane = tid & 31;
    const int      w    = tid >> 5;          // 0..7 -> col group w*16
    const int      c0   = blockIdx.x * TMR;

    // A-build mapping: 8 threads per row; thread covers 8 floats (16B bf16)
    const int ar = tid >> 3;          // row 0..31
    const int ap = tid & 7;           // part: floats [ap*8, ap*8+8)

    float acc[2][2][4];
#pragma unroll
    for (int mt = 0; mt < 2; ++mt)
#pragma unroll
        for (int nt = 0; nt < 2; ++nt)
#pragma unroll
            for (int q = 0; q < 4; ++q) acc[mt][nt][q] = 0.0f;

    const int*   srow = edge_src + (size_t)(c0 + ar) * P;
    const float* crow = g_coef + (size_t)(c0 + ar) * P;

    // STS A hi/lo into stage st from registers (8 floats -> 16B hi + 16B lo).
    auto sts_a = [&](uint32_t st, const float4* xv, float c) {
        float a0 = xv[0].x * c, a1 = xv[0].y * c, a2 = xv[0].z * c, a3 = xv[0].w * c;
        float a4 = xv[1].x * c, a5 = xv[1].y * c, a6 = xv[1].z * c, a7 = xv[1].w * c;
        float r0, r1, r2, r3, r4, r5, r6, r7;
        uint4 h, l;
        h.x = pack_hi(a0, a1, r0, r1); h.y = pack_hi(a2, a3, r2, r3);
        h.z = pack_hi(a4, a5, r4, r5); h.w = pack_hi(a6, a7, r6, r7);
        l.x = pack2(r0, r1); l.y = pack2(r2, r3);
        l.z = pack2(r4, r5); l.w = pack2(r6, r7);
        char* pa = smem + A_OFF(st) + (uint32_t)ar * LDA + (uint32_t)ap * 16;
        *(uint4*)(pa)        = h;
        *(uint4*)(pa + AL_D) = l;
    };
    // cp.async W[k] (hi+lo, each 1024 16B-chunks) + commit.
    auto cp_w = [&](uint32_t st, int k) {
#pragma unroll
        for (int hl = 0; hl < 2; ++hl) {
            uint32_t    wd = sb + W_OFF(st) + hl * WL_D;
            const char* ws = (const char*)(g_wimg + ((size_t)k * 2 + hl) * 4096);
#pragma unroll
            for (int jj = 0; jj < 4; ++jj) {
                int j = tid + 256 * jj;   // [0, 1024)
                cp_async16(wd + (uint32_t)(j >> 3) * LDA + (uint32_t)(j & 7) * 16,
                           ws + (size_t)j * 16);
            }
        }
        asm volatile("cp.async.commit_group;" ::: "memory");
    };

    // Prologue: A[0]/W[0] -> stage0, prefetch xv for k=1, wait + barrier.
    float4 xv[2];
    {
        int src0 = srow[0];
        const float4* xr = (const float4*)(x + (size_t)src0 * IN_F) + ap * 2;
        xv[0] = xr[0]; xv[1] = xr[1];
        sts_a(0, xv, crow[0]);
    }
    cp_w(0, 0);
    {
        int src1 = srow[1];
        const float4* xr = (const float4*)(x + (size_t)src1 * IN_F) + ap * 2;
        xv[0] = xr[0]; xv[1] = xr[1];
    }
    asm volatile("cp.async.wait_group 0;" ::: "memory");
    __syncthreads();

#pragma unroll 1
    for (int k = 0; k < P; ++k) {
        const uint32_t s  = (uint32_t)(k & 1);
        const uint32_t ns = s ^ 1u;
        const int      kn = (k + 1) & 15;

        // W[k+1]/A[k+1] -> stage ns (overlaps with this k's MMAs).
        cp_w(ns, kn);
        sts_a(ns, xv, crow[kn]);
        // Prefetch xv for k+2.
        {
            int srcn = srow[(k + 2) & 15];
            const float4* xr = (const float4*)(x + (size_t)srcn * IN_F) + ap * 2;
            xv[0] = xr[0]; xv[1] = xr[1];
        }

        // MMA over stage s: 4 ksteps of 16, warp tile 32x16.
        const uint32_t aBase = sb + A_OFF(s) +
            (uint32_t)(lane & 15) * LDA + (uint32_t)(lane >> 4) * 16;
        const uint32_t bBase = sb + W_OFF(s) +
            (uint32_t)(w * 16 + ((lane >> 4) << 3) + (lane & 7)) * LDA +
            (uint32_t)((lane >> 3) & 1) * 16;
#pragma unroll
        for (int ks = 0; ks < 4; ++ks) {
            uint32_t ah[2][4], al[2][4], bh[4], bl[4];
            uint32_t ao = aBase + (uint32_t)ks * 32;
            uint32_t bo = bBase + (uint32_t)ks * 32;
            LDSM4(ah[0], ao);
            LDSM4(ah[1], ao + 16 * LDA);
            LDSM4(bh, bo);
            LDSM4(al[0], ao + AL_D);
            LDSM4(al[1], ao + AL_D + 16 * LDA);
            LDSM4(bl, bo + WL_D);

            // Pass-outer order: 4 independent accumulators between reuses.
#pragma unroll
            for (int mt = 0; mt < 2; ++mt)
#pragma unroll
                for (int nt = 0; nt < 2; ++nt)
                    MMA(acc[mt][nt], ah[mt], bh[2 * nt], bh[2 * nt + 1]);
#pragma unroll
            for (int mt = 0; mt < 2; ++mt)
#pragma unroll
                for (int nt = 0; nt < 2; ++nt)
                    MMA(acc[mt][nt], ah[mt], bl[2 * nt], bl[2 * nt + 1]);
#pragma unroll
            for (int mt = 0; mt < 2; ++mt)
#pragma unroll
                for (int nt = 0; nt < 2; ++nt)
                    MMA(acc[mt][nt], al[mt], bh[2 * nt], bh[2 * nt + 1]);
        }

        // Wait for next W then release both stages.
        asm volatile("cp.async.wait_group 0;" ::: "memory");
        __syncthreads();
    }

    // Epilogue: write [32,128] tile.
#pragma unroll
    for (int mt = 0; mt < 2; ++mt)
#pragma unroll
        for (int nt = 0; nt < 2; ++nt) {
            int    row = c0 + mt * 16 + (lane >> 2);
            int    col = w * 16 + nt * 8 + (lane & 3) * 2;
            float* o   = out + (size_t)row * OUT_F + col;
            *(float2*)o               = make_float2(acc[mt][nt][0], acc[mt][nt][1]);
            *(float2*)(o + 8 * OUT_F) = make_float2(acc[mt][nt][2], acc[mt][nt][3]);
        }
}

extern "C" void kernel_launch(void* const* d_in, const int* in_sizes, int n_in,
                              void* d_out, int out_size)
{
    const float* x        = (const float*)d_in[0];
    const float* pos      = (const float*)d_in[1];
    const int*   edge_src = (const int*)  d_in[2];
    const int*   edge_tgt = (const int*)  d_in[3];
    const float* kpts     = (const float*)d_in[4];
    const float* kw       = (const float*)d_in[5];
    float*       out      = (float*)d_out;

    cudaFuncSetAttribute(kp_mma_kernel,
                         cudaFuncAttributeMaxDynamicSharedMemorySize, SMEM_DYN);

    kp_prep_kernel<<<576, 256>>>(pos, edge_src, edge_tgt, kpts, kw);
    kp_mma_kernel<<<NC / TMR, 256, SMEM_DYN>>>(x, edge_src, out);
}